// round 10
// baseline (speedup 1.0000x reference)
#include <cuda_runtime.h>
#include <cuda_bf16.h>
#include <math_constants.h>
#include <cstdint>

// Problem constants
#define NROWS 16384   // 64 * 256
#define DIM   1024
#define CB    4096

// Output layout (flattened tuple, float32):
//   quantized_st [16384*1024], codes [16384], probs [16384*4096], vq_loss [1]
#define QUANT_OFF 0
#define CODES_OFF 16777216
#define PROBS_OFF 16793600
#define LOSS_OFF  83902464

// ---------------------------------------------------------------------------
// Scratch (device globals — no allocations allowed)
// ---------------------------------------------------------------------------
__device__ float  g_S[(size_t)NROWS * CB];            // 256 MiB distances
__device__ float  g_cnorm[CB];
__device__ double g_loss;
__device__ __nv_bfloat16 g_Ahi[(size_t)NROWS * DIM];  // 32 MiB
__device__ __nv_bfloat16 g_Alo[(size_t)NROWS * DIM];  // 32 MiB
__device__ __nv_bfloat16 g_Bhi[(size_t)CB * DIM];     //  8 MiB
__device__ __nv_bfloat16 g_Blo[(size_t)CB * DIM];     //  8 MiB

// ---------------------------------------------------------------------------
// Low-level helpers (plain sm_80+ PTX — safe through the compute_103 stage)
// ---------------------------------------------------------------------------
__device__ __forceinline__ uint32_t smem_u32(const void* p) {
    uint32_t a;
    asm("{ .reg .u64 t; cvta.to.shared.u64 t, %1; cvt.u32.u64 %0, t; }"
        : "=r"(a) : "l"(p));
    return a;
}

__device__ __forceinline__ void cp_async16(uint32_t saddr, const void* gaddr) {
    asm volatile("cp.async.cg.shared.global [%0], [%1], 16;"
                 :: "r"(saddr), "l"(gaddr));
}
#define CP_COMMIT() asm volatile("cp.async.commit_group;" ::: "memory")
#define CP_WAIT_1() asm volatile("cp.async.wait_group 1;" ::: "memory")
#define CP_WAIT_0() asm volatile("cp.async.wait_group 0;" ::: "memory")

__device__ __forceinline__ void ldsm_x4(uint32_t* r, uint32_t addr) {
    asm volatile("ldmatrix.sync.aligned.m8n8.x4.shared.b16 {%0,%1,%2,%3}, [%4];"
                 : "=r"(r[0]), "=r"(r[1]), "=r"(r[2]), "=r"(r[3]) : "r"(addr));
}

__device__ __forceinline__ void mma16816(float* c, const uint32_t* a, const uint32_t* b) {
    asm volatile(
        "mma.sync.aligned.m16n8k16.row.col.f32.bf16.bf16.f32 "
        "{%0,%1,%2,%3}, {%4,%5,%6,%7}, {%8,%9}, {%0,%1,%2,%3};"
        : "+f"(c[0]), "+f"(c[1]), "+f"(c[2]), "+f"(c[3])
        : "r"(a[0]), "r"(a[1]), "r"(a[2]), "r"(a[3]), "r"(b[0]), "r"(b[1]));
}

// ---------------------------------------------------------------------------
// Kernel 0: codebook norms + zero the loss accumulator
// ---------------------------------------------------------------------------
__global__ __launch_bounds__(256) void cnorm_kernel(const float* __restrict__ cb) {
    int row = blockIdx.x;
    const float4* c4 = (const float4*)(cb + (size_t)row * DIM);
    float4 v = c4[threadIdx.x];
    float s = v.x * v.x + v.y * v.y + v.z * v.z + v.w * v.w;
    #pragma unroll
    for (int o = 16; o > 0; o >>= 1) s += __shfl_xor_sync(0xffffffffu, s, o);
    __shared__ float ws[8];
    if ((threadIdx.x & 31) == 0) ws[threadIdx.x >> 5] = s;
    __syncthreads();
    if (threadIdx.x == 0) {
        float t = 0.f;
        #pragma unroll
        for (int i = 0; i < 8; i++) t += ws[i];
        g_cnorm[row] = t;
        if (row == 0) g_loss = 0.0;
    }
}

// ---------------------------------------------------------------------------
// Kernel 0b: split fp32 inputs into bf16 hi/lo pairs
// ---------------------------------------------------------------------------
#define A_F4 ((size_t)NROWS * DIM / 4)   // 4194304
#define B_F4 ((size_t)CB * DIM / 4)      // 1048576

__global__ __launch_bounds__(256) void split_kernel(const float* __restrict__ A,
                                                    const float* __restrict__ B) {
    size_t i4 = (size_t)blockIdx.x * 256 + threadIdx.x;
    float4 v;
    __nv_bfloat16 *hi, *lo;
    size_t e;
    if (i4 < A_F4) {
        v = ((const float4*)A)[i4];
        hi = g_Ahi; lo = g_Alo; e = i4 * 4;
    } else {
        size_t j = i4 - A_F4;
        v = ((const float4*)B)[j];
        hi = g_Bhi; lo = g_Blo; e = j * 4;
    }
    __nv_bfloat16 h0 = __float2bfloat16_rn(v.x);
    __nv_bfloat16 h1 = __float2bfloat16_rn(v.y);
    __nv_bfloat16 h2 = __float2bfloat16_rn(v.z);
    __nv_bfloat16 h3 = __float2bfloat16_rn(v.w);
    __nv_bfloat16 l0 = __float2bfloat16_rn(v.x - __bfloat162float(h0));
    __nv_bfloat16 l1 = __float2bfloat16_rn(v.y - __bfloat162float(h1));
    __nv_bfloat16 l2 = __float2bfloat16_rn(v.z - __bfloat162float(h2));
    __nv_bfloat16 l3 = __float2bfloat16_rn(v.w - __bfloat162float(h3));
    __nv_bfloat162* hp = (__nv_bfloat162*)(hi + e);
    __nv_bfloat162* lp = (__nv_bfloat162*)(lo + e);
    hp[0] = __halves2bfloat162(h0, h1);
    hp[1] = __halves2bfloat162(h2, h3);
    lp[0] = __halves2bfloat162(l0, l1);
    lp[1] = __halves2bfloat162(l2, l3);
}

// ---------------------------------------------------------------------------
// Kernel 1: bf16x3 HMMA GEMM -> g_S[m][n] = cnorm[n] - 2 * dot(A_m, B_n)
// 128x128 CTA tile, BK=32, cp.async double buffer, 256 threads (8 warps).
// Warp layout: 2(M) x 4(N) -> each warp owns 64x32.
// SMEM tiles padded to 80B rows: ldmatrix 8-row phases hit banks 20r mod 32
// -> all 32 banks distinct -> conflict-free.
// ---------------------------------------------------------------------------
#define GBM 128
#define GBN 128
#define BKC 32                  // K per chunk (bf16 elems)
#define NCHUNK (DIM / BKC)      // 32
#define PKROW 40                // padded row length (bf16) = 80 bytes
#define ROWB  (PKROW * 2)       // 80
#define TILE_B (128 * ROWB)     // 10240 bytes per tile
#define STAGE_BYTES (4 * TILE_B)            // 40960
#define GEMM_SMEM_TOTAL (2 * STAGE_BYTES)   // 81920

__device__ __forceinline__ void load_stage(uint32_t st, int m0, int n0, int k0, int tid) {
    // 4 tiles x 128 rows x 64B (4 x 16B chunks). 2048 cp.async / 256 thr = 8 each.
    const char* gbase[4] = {(const char*)g_Ahi, (const char*)g_Alo,
                            (const char*)g_Bhi, (const char*)g_Blo};
    #pragma unroll
    for (int tile = 0; tile < 4; tile++) {
        int rc0 = (tile < 2) ? m0 : n0;
        #pragma unroll
        for (int r = 0; r < 2; r++) {
            int idx = tid + r * 256;          // 0..511
            int row = idx >> 2;               // 0..127
            int ch  = idx & 3;                // 0..3
            uint32_t saddr = st + tile * TILE_B + (uint32_t)row * ROWB + (uint32_t)ch * 16;
            const char* g = gbase[tile] + ((size_t)(rc0 + row) * DIM + k0) * 2 + (size_t)ch * 16;
            cp_async16(saddr, g);
        }
    }
}

__global__ __launch_bounds__(256, 2) void gemm_kernel() {
    extern __shared__ __align__(128) char smem[];
    const uint32_t smem_base = smem_u32(smem);
    const int tid   = threadIdx.x;
    const int wid   = tid >> 5;
    const int lane  = tid & 31;
    const int group = lane >> 2;    // 0..7
    const int tig   = lane & 3;     // 0..3
    const int warp_m = wid >> 2;    // 0..1 (64 rows each)
    const int warp_n = wid & 3;     // 0..3 (32 cols each)
    const int n0 = blockIdx.x * GBN;
    const int m0 = blockIdx.y * GBM;

    // Per-lane ldmatrix base offsets (within a stage), excluding kb/tile terms.
    // A (m16k16, .x4): lanes 0-7 rows r0-7 @k-lo | 8-15 rows r8-15 @k-lo |
    //                  16-23 rows r0-7 @k-hi | 24-31 rows r8-15 @k-hi
    const uint32_t a_off =
        (uint32_t)(warp_m * 64 + (lane & 7) + 8 * ((lane >> 3) & 1)) * ROWB
        + ((uint32_t)(lane >> 4) * 16);
    // B (two n8k16 frags per .x4): lanes 0-7 n0-7 @k-lo | 8-15 n0-7 @k-hi |
    //                              16-23 n8-15 @k-lo | 24-31 n8-15 @k-hi
    const uint32_t b_off = 2 * TILE_B
        + (uint32_t)(warp_n * 32 + (lane & 7) + 8 * (lane >> 4)) * ROWB
        + ((uint32_t)((lane >> 3) & 1) * 16);

    float acc[4][4][4];             // [mt][nt][frag]
    #pragma unroll
    for (int i = 0; i < 4; i++)
        #pragma unroll
        for (int j = 0; j < 4; j++)
            #pragma unroll
            for (int k = 0; k < 4; k++) acc[i][j][k] = 0.f;

    // Prologue: chunks 0 and 1
    load_stage(smem_base, m0, n0, 0, tid);
    CP_COMMIT();
    load_stage(smem_base + STAGE_BYTES, m0, n0, BKC, tid);
    CP_COMMIT();

    #pragma unroll 1
    for (int i = 0; i < NCHUNK; i++) {
        if (i < NCHUNK - 1) CP_WAIT_1(); else CP_WAIT_0();
        __syncthreads();
        const uint32_t st = smem_base + (i & 1) * STAGE_BYTES;
        const uint32_t a_base = st + a_off;
        const uint32_t b_base = st + b_off;

        #pragma unroll
        for (int k16 = 0; k16 < 2; k16++) {
            const uint32_t kb = k16 * 32;   // 16 bf16 = 32 bytes

            uint32_t a[4][4], bh[4][2], bl[4][2];
            // B_hi / B_lo fragments: 4 ldmatrix.x4 (each covers 2 n-tiles)
            #pragma unroll
            for (int p = 0; p < 2; p++) {
                uint32_t t[4];
                uint32_t bd = b_base + (uint32_t)p * (16 * ROWB) + kb;
                ldsm_x4(t, bd);
                bh[2 * p][0] = t[0]; bh[2 * p][1] = t[1];
                bh[2 * p + 1][0] = t[2]; bh[2 * p + 1][1] = t[3];
                ldsm_x4(t, bd + TILE_B);
                bl[2 * p][0] = t[0]; bl[2 * p][1] = t[1];
                bl[2 * p + 1][0] = t[2]; bl[2 * p + 1][1] = t[3];
            }
            // A_hi fragments: 4 ldmatrix.x4
            #pragma unroll
            for (int mt = 0; mt < 4; mt++)
                ldsm_x4(a[mt], a_base + (uint32_t)mt * (16 * ROWB) + kb);
            // hi*hi and hi*lo
            #pragma unroll
            for (int mt = 0; mt < 4; mt++)
                #pragma unroll
                for (int nt = 0; nt < 4; nt++) {
                    mma16816(acc[mt][nt], a[mt], bh[nt]);
                    mma16816(acc[mt][nt], a[mt], bl[nt]);
                }
            // A_lo fragments (overwrite a), then lo*hi
            #pragma unroll
            for (int mt = 0; mt < 4; mt++)
                ldsm_x4(a[mt], a_base + TILE_B + (uint32_t)mt * (16 * ROWB) + kb);

            if (k16 == 1) {
                // All reads of this stage are now in registers -> safe to refill.
                __syncthreads();
                if (i + 2 < NCHUNK) {
                    load_stage(st, m0, n0, (i + 2) * BKC, tid);
                    CP_COMMIT();
                }
            }

            #pragma unroll
            for (int mt = 0; mt < 4; mt++)
                #pragma unroll
                for (int nt = 0; nt < 4; nt++)
                    mma16816(acc[mt][nt], a[mt], bh[nt]);
        }
    }

    // Epilogue: s = cnorm[n] - 2*dot
    #pragma unroll
    for (int nt = 0; nt < 4; nt++) {
        const int n = n0 + warp_n * 32 + nt * 8 + tig * 2;
        const float2 cn = *(const float2*)(g_cnorm + n);
        #pragma unroll
        for (int mt = 0; mt < 4; mt++) {
            const int m = m0 + warp_m * 64 + mt * 16 + group;
            float2 o0, o1;
            o0.x = cn.x - 2.f * acc[mt][nt][0];
            o0.y = cn.y - 2.f * acc[mt][nt][1];
            o1.x = cn.x - 2.f * acc[mt][nt][2];
            o1.y = cn.y - 2.f * acc[mt][nt][3];
            *(float2*)(g_S + (size_t)m * CB + n) = o0;
            *(float2*)(g_S + (size_t)(m + 8) * CB + n) = o1;
        }
    }
}

// ---------------------------------------------------------------------------
// Kernel 2: per-row argmin(+double refinement), softmax -> probs,
//           gather -> quantized, loss accumulation, codes.
// ---------------------------------------------------------------------------
__global__ __launch_bounds__(256) void row_kernel(const float* __restrict__ slot,
                                                  const float* __restrict__ cb,
                                                  float* __restrict__ out) {
    const int row = blockIdx.x;
    const int tid = threadIdx.x;
    const float* srow = g_S + (size_t)row * CB;

    // --- load row, track local top-2 (first-occurrence tie-break) ---
    float v[16];
    float m1 = CUDART_INF_F, m2 = CUDART_INF_F;
    int   i1 = CB, i2 = CB;
    #pragma unroll
    for (int i = 0; i < 16; i++) {
        int idx = tid + i * 256;
        float x = srow[idx];
        v[i] = x;
        if (x < m1 || (x == m1 && idx < i1)) {
            m2 = m1; i2 = i1; m1 = x; i1 = idx;
        } else if (x < m2 || (x == m2 && idx < i2)) {
            m2 = x; i2 = idx;
        }
    }

    // --- block-wide top-2 reduction ---
    __shared__ float rm1[256], rm2[256];
    __shared__ int   ri1[256], ri2[256];
    rm1[tid] = m1; rm2[tid] = m2; ri1[tid] = i1; ri2[tid] = i2;
    __syncthreads();
    for (int s = 128; s > 0; s >>= 1) {
        if (tid < s) {
            float a1 = rm1[tid], b1 = rm1[tid + s];
            int   ai = ri1[tid], bi = ri1[tid + s];
            float a2 = rm2[tid], b2 = rm2[tid + s];
            int  a2i = ri2[tid], b2i = ri2[tid + s];
            bool af = (a1 < b1) || (a1 == b1 && ai < bi);
            if (af) {
                bool t = (a2 < b1) || (a2 == b1 && a2i < bi);
                rm2[tid] = t ? a2 : b1;  ri2[tid] = t ? a2i : bi;
            } else {
                rm1[tid] = b1; ri1[tid] = bi;
                bool t = (b2 < a1) || (b2 == a1 && b2i < ai);
                rm2[tid] = t ? b2 : a1;  ri2[tid] = t ? b2i : ai;
            }
        }
        __syncthreads();
    }
    const float gm1 = rm1[0]; const int gi1 = ri1[0];
    const float gm2 = rm2[0]; const int gi2 = ri2[0];
    __syncthreads();

    // --- rare-path double-precision refinement of argmin ---
    __shared__ int    s_code;
    __shared__ double sd[256];
    if (gm2 - gm1 < 1e-3f) {
        const float* x  = slot + (size_t)row * DIM;
        const float* c1 = cb + (size_t)gi1 * DIM;
        const float* c2 = cb + (size_t)gi2 * DIM;
        double d1 = 0.0, d2 = 0.0;
        for (int k = tid; k < DIM; k += 256) {
            double xv = (double)x[k];
            double a  = (double)c1[k];
            double b  = (double)c2[k];
            d1 += a * (a - 2.0 * xv);
            d2 += b * (b - 2.0 * xv);
        }
        sd[tid] = d1; __syncthreads();
        for (int s = 128; s > 0; s >>= 1) { if (tid < s) sd[tid] += sd[tid + s]; __syncthreads(); }
        double D1 = sd[0]; __syncthreads();
        sd[tid] = d2; __syncthreads();
        for (int s = 128; s > 0; s >>= 1) { if (tid < s) sd[tid] += sd[tid + s]; __syncthreads(); }
        double D2 = sd[0];
        if (tid == 0)
            s_code = (D2 < D1 || (D2 == D1 && gi2 < gi1)) ? gi2 : gi1;
    } else if (tid == 0) {
        s_code = gi1;
    }
    __syncthreads();
    const int code = s_code;

    // --- softmax over -s (row constant ||x||^2 cancels) ---
    float lsum = 0.f;
    #pragma unroll
    for (int i = 0; i < 16; i++) {
        float e = __expf(gm1 - v[i]);   // arg <= 0
        v[i] = e;
        lsum += e;
    }
    rm1[tid] = lsum; __syncthreads();
    for (int s = 128; s > 0; s >>= 1) { if (tid < s) rm1[tid] += rm1[tid + s]; __syncthreads(); }
    const float inv = 1.0f / rm1[0];
    float* probs = out + PROBS_OFF + (size_t)row * CB;
    #pragma unroll
    for (int i = 0; i < 16; i++)
        probs[tid + i * 256] = v[i] * inv;

    // --- quantized gather + loss contribution ---
    const float4* c4 = (const float4*)(cb + (size_t)code * DIM);
    const float4* x4 = (const float4*)(slot + (size_t)row * DIM);
    float4 q = c4[tid];
    float4 x = x4[tid];
    ((float4*)(out + QUANT_OFF + (size_t)row * DIM))[tid] = q;
    float dx = x.x - q.x, dy = x.y - q.y, dz = x.z - q.z, dw = x.w - q.w;
    float ls = dx * dx + dy * dy + dz * dz + dw * dw;

    __syncthreads();
    rm1[tid] = ls; __syncthreads();
    for (int s = 128; s > 0; s >>= 1) { if (tid < s) rm1[tid] += rm1[tid + s]; __syncthreads(); }
    if (tid == 0) {
        atomicAdd(&g_loss, (double)rm1[0]);
        out[CODES_OFF + row] = (float)code;
    }
}

// ---------------------------------------------------------------------------
// Kernel 3: finalize vq_loss = 1.25 * mean((x - q)^2)
// ---------------------------------------------------------------------------
__global__ void finish_kernel(float* __restrict__ out) {
    out[LOSS_OFF] = (float)(1.25 * g_loss / (double)((size_t)NROWS * DIM));
}

// ---------------------------------------------------------------------------
extern "C" void kernel_launch(void* const* d_in, const int* in_sizes, int n_in,
                              void* d_out, int out_size) {
    const float* slot = (const float*)d_in[0];   // [64,256,1024] f32
    const float* cb   = (const float*)d_in[1];   // [4096,1024]  f32
    float* out = (float*)d_out;

    // Dynamic smem opt-in (host-side attribute; idempotent; capture-safe)
    cudaFuncSetAttribute(gemm_kernel, cudaFuncAttributeMaxDynamicSharedMemorySize,
                         GEMM_SMEM_TOTAL);

    cnorm_kernel<<<CB, 256>>>(cb);
    split_kernel<<<(unsigned)((A_F4 + B_F4) / 256), 256>>>(slot, cb);
    dim3 grid(CB / GBN, NROWS / GBM);            // 32 x 128
    gemm_kernel<<<grid, 256, GEMM_SMEM_TOTAL>>>();
    row_kernel<<<NROWS, 256>>>(slot, cb, out);
    finish_kernel<<<1, 1>>>(out);
}

// round 11
// speedup vs baseline: 1.2375x; 1.2375x over previous
#include <cuda_runtime.h>
#include <cuda_bf16.h>
#include <math_constants.h>
#include <cstdint>

// Problem constants
#define NROWS 16384   // 64 * 256
#define DIM   1024
#define CB    4096

// Output layout (flattened tuple, float32):
//   quantized_st [16384*1024], codes [16384], probs [16384*4096], vq_loss [1]
#define QUANT_OFF 0
#define CODES_OFF 16777216
#define PROBS_OFF 16793600
#define LOSS_OFF  83902464

// ---------------------------------------------------------------------------
// Scratch (device globals — no allocations allowed)
// ---------------------------------------------------------------------------
__device__ float  g_S[(size_t)NROWS * CB];            // 256 MiB distances
__device__ float  g_cnorm[CB];
__device__ double g_loss;
__device__ __nv_bfloat16 g_Ahi[(size_t)NROWS * DIM];  // 32 MiB
__device__ __nv_bfloat16 g_Alo[(size_t)NROWS * DIM];  // 32 MiB
__device__ __nv_bfloat16 g_Bhi[(size_t)CB * DIM];     //  8 MiB
__device__ __nv_bfloat16 g_Blo[(size_t)CB * DIM];     //  8 MiB

// ---------------------------------------------------------------------------
// Low-level helpers (plain sm_80+ PTX — safe through the compute_103 stage)
// ---------------------------------------------------------------------------
__device__ __forceinline__ uint32_t smem_u32(const void* p) {
    uint32_t a;
    asm("{ .reg .u64 t; cvta.to.shared.u64 t, %1; cvt.u32.u64 %0, t; }"
        : "=r"(a) : "l"(p));
    return a;
}

__device__ __forceinline__ void cp_async16(uint32_t saddr, const void* gaddr) {
    asm volatile("cp.async.cg.shared.global [%0], [%1], 16;"
                 :: "r"(saddr), "l"(gaddr));
}
#define CP_COMMIT() asm volatile("cp.async.commit_group;" ::: "memory")
#define CP_WAIT_1() asm volatile("cp.async.wait_group 1;" ::: "memory")
#define CP_WAIT_0() asm volatile("cp.async.wait_group 0;" ::: "memory")

__device__ __forceinline__ uint32_t lds32(uint32_t a) {
    uint32_t v;
    asm("ld.shared.b32 %0, [%1];" : "=r"(v) : "r"(a));
    return v;
}

__device__ __forceinline__ void mma16816(float* c, const uint32_t* a, const uint32_t* b) {
    asm volatile(
        "mma.sync.aligned.m16n8k16.row.col.f32.bf16.bf16.f32 "
        "{%0,%1,%2,%3}, {%4,%5,%6,%7}, {%8,%9}, {%0,%1,%2,%3};"
        : "+f"(c[0]), "+f"(c[1]), "+f"(c[2]), "+f"(c[3])
        : "r"(a[0]), "r"(a[1]), "r"(a[2]), "r"(a[3]), "r"(b[0]), "r"(b[1]));
}

// ---------------------------------------------------------------------------
// Kernel 0: codebook norms + zero the loss accumulator
// ---------------------------------------------------------------------------
__global__ __launch_bounds__(256) void cnorm_kernel(const float* __restrict__ cb) {
    int row = blockIdx.x;
    const float4* c4 = (const float4*)(cb + (size_t)row * DIM);
    float4 v = c4[threadIdx.x];
    float s = v.x * v.x + v.y * v.y + v.z * v.z + v.w * v.w;
    #pragma unroll
    for (int o = 16; o > 0; o >>= 1) s += __shfl_xor_sync(0xffffffffu, s, o);
    __shared__ float ws[8];
    if ((threadIdx.x & 31) == 0) ws[threadIdx.x >> 5] = s;
    __syncthreads();
    if (threadIdx.x == 0) {
        float t = 0.f;
        #pragma unroll
        for (int i = 0; i < 8; i++) t += ws[i];
        g_cnorm[row] = t;
        if (row == 0) g_loss = 0.0;
    }
}

// ---------------------------------------------------------------------------
// Kernel 0b: split fp32 inputs into bf16 hi/lo pairs
// ---------------------------------------------------------------------------
#define A_F4 ((size_t)NROWS * DIM / 4)   // 4194304
#define B_F4 ((size_t)CB * DIM / 4)      // 1048576

__global__ __launch_bounds__(256) void split_kernel(const float* __restrict__ A,
                                                    const float* __restrict__ B) {
    size_t i4 = (size_t)blockIdx.x * 256 + threadIdx.x;
    float4 v;
    __nv_bfloat16 *hi, *lo;
    size_t e;
    if (i4 < A_F4) {
        v = ((const float4*)A)[i4];
        hi = g_Ahi; lo = g_Alo; e = i4 * 4;
    } else {
        size_t j = i4 - A_F4;
        v = ((const float4*)B)[j];
        hi = g_Bhi; lo = g_Blo; e = j * 4;
    }
    __nv_bfloat16 h0 = __float2bfloat16_rn(v.x);
    __nv_bfloat16 h1 = __float2bfloat16_rn(v.y);
    __nv_bfloat16 h2 = __float2bfloat16_rn(v.z);
    __nv_bfloat16 h3 = __float2bfloat16_rn(v.w);
    __nv_bfloat16 l0 = __float2bfloat16_rn(v.x - __bfloat162float(h0));
    __nv_bfloat16 l1 = __float2bfloat16_rn(v.y - __bfloat162float(h1));
    __nv_bfloat16 l2 = __float2bfloat16_rn(v.z - __bfloat162float(h2));
    __nv_bfloat16 l3 = __float2bfloat16_rn(v.w - __bfloat162float(h3));
    __nv_bfloat162* hp = (__nv_bfloat162*)(hi + e);
    __nv_bfloat162* lp = (__nv_bfloat162*)(lo + e);
    hp[0] = __halves2bfloat162(h0, h1);
    hp[1] = __halves2bfloat162(h2, h3);
    lp[0] = __halves2bfloat162(l0, l1);
    lp[1] = __halves2bfloat162(l2, l3);
}

// ---------------------------------------------------------------------------
// Kernel 1: bf16x3 HMMA GEMM -> g_S[m][n] = cnorm[n] - 2 * dot(A_m, B_n)
// 128x128 CTA tile, BK=32, 3-stage cp.async pipeline, 256 threads (8 warps).
// Warp layout: 2(M) x 4(N) -> each warp owns 64x32.
// SMEM tiles padded to 80B rows (banks 20r mod 32 distinct) -> conflict-free.
// 3 stages => the buffer refilled for chunk i+2 is (i-1)%3, whose readers are
// provably past the top-of-chunk barrier: loads issue BEFORE compute, no
// second barrier per chunk, cp.async burst hides under the 96 MMAs.
// ---------------------------------------------------------------------------
#define GBM 128
#define GBN 128
#define BKC 32                  // K per chunk (bf16 elems)
#define NCHUNK (DIM / BKC)      // 32
#define PKROW 40                // padded row length (bf16) = 80 bytes
#define ROWB  (PKROW * 2)       // 80
#define TILE_B (128 * ROWB)     // 10240 bytes per tile
#define STAGE_BYTES (4 * TILE_B)            // 40960
#define NSTAGE 3
#define GEMM_SMEM_TOTAL (NSTAGE * STAGE_BYTES)   // 122880

__device__ __forceinline__ void load_stage(uint32_t st, int m0, int n0, int k0, int tid) {
    // 4 tiles x 128 rows x 64B (4 x 16B chunks). 2048 cp.async / 256 thr = 8 each.
    const char* gbase[4] = {(const char*)g_Ahi, (const char*)g_Alo,
                            (const char*)g_Bhi, (const char*)g_Blo};
    #pragma unroll
    for (int tile = 0; tile < 4; tile++) {
        int rc0 = (tile < 2) ? m0 : n0;
        #pragma unroll
        for (int r = 0; r < 2; r++) {
            int idx = tid + r * 256;          // 0..511
            int row = idx >> 2;               // 0..127
            int ch  = idx & 3;                // 0..3
            uint32_t saddr = st + tile * TILE_B + (uint32_t)row * ROWB + (uint32_t)ch * 16;
            const char* g = gbase[tile] + ((size_t)(rc0 + row) * DIM + k0) * 2 + (size_t)ch * 16;
            cp_async16(saddr, g);
        }
    }
}

__global__ __launch_bounds__(256, 1) void gemm_kernel() {
    extern __shared__ __align__(128) char smem[];
    const uint32_t smem_base = smem_u32(smem);
    const int tid   = threadIdx.x;
    const int wid   = tid >> 5;
    const int lane  = tid & 31;
    const int group = lane >> 2;    // 0..7
    const int tig   = lane & 3;     // 0..3
    const int warp_m = wid >> 2;    // 0..1 (64 rows each)
    const int warp_n = wid & 3;     // 0..3 (32 cols each)
    const int n0 = blockIdx.x * GBN;
    const int m0 = blockIdx.y * GBM;

    float acc[4][4][4];             // [mt][nt][frag]
    #pragma unroll
    for (int i = 0; i < 4; i++)
        #pragma unroll
        for (int j = 0; j < 4; j++)
            #pragma unroll
            for (int k = 0; k < 4; k++) acc[i][j][k] = 0.f;

    // Prologue: chunks 0 and 1 into stages 0 and 1
    load_stage(smem_base, m0, n0, 0, tid);
    CP_COMMIT();
    load_stage(smem_base + STAGE_BYTES, m0, n0, BKC, tid);
    CP_COMMIT();

    int st_idx = 0;       // stage holding chunk i
    #pragma unroll 1
    for (int i = 0; i < NCHUNK; i++) {
        if (i < NCHUNK - 1) CP_WAIT_1(); else CP_WAIT_0();
        __syncthreads();   // chunk i data visible to all; chunk i-1 readers done

        // Prefetch chunk i+2 into stage (i+2)%3 == (i-1)%3 (free after barrier)
        if (i + 2 < NCHUNK) {
            int nst = st_idx + 2; if (nst >= NSTAGE) nst -= NSTAGE;
            load_stage(smem_base + (uint32_t)nst * STAGE_BYTES, m0, n0, (i + 2) * BKC, tid);
            CP_COMMIT();
        }

        const uint32_t st = smem_base + (uint32_t)st_idx * STAGE_BYTES;

        #pragma unroll
        for (int k16 = 0; k16 < 2; k16++) {
            const uint32_t kb = k16 * 32;   // 16 bf16 = 32 bytes

            uint32_t a[4][4], bh[4][2], bl[4][2];
            // A_hi fragments (tile 0)
            #pragma unroll
            for (int mt = 0; mt < 4; mt++) {
                uint32_t ad = st + (uint32_t)(warp_m * 64 + mt * 16 + group) * ROWB + kb + tig * 4;
                a[mt][0] = lds32(ad);
                a[mt][1] = lds32(ad + 8 * ROWB);
                a[mt][2] = lds32(ad + 16);
                a[mt][3] = lds32(ad + 8 * ROWB + 16);
            }
            // B_hi (tile 2) and B_lo (tile 3) fragments
            #pragma unroll
            for (int nt = 0; nt < 4; nt++) {
                uint32_t bd = st + 2 * TILE_B + (uint32_t)(warp_n * 32 + nt * 8 + group) * ROWB + kb + tig * 4;
                bh[nt][0] = lds32(bd);
                bh[nt][1] = lds32(bd + 16);
                bl[nt][0] = lds32(bd + TILE_B);
                bl[nt][1] = lds32(bd + TILE_B + 16);
            }
            // hi*hi and hi*lo
            #pragma unroll
            for (int mt = 0; mt < 4; mt++)
                #pragma unroll
                for (int nt = 0; nt < 4; nt++) {
                    mma16816(acc[mt][nt], a[mt], bh[nt]);
                    mma16816(acc[mt][nt], a[mt], bl[nt]);
                }
            // A_lo fragments (tile 1), reuse B_hi: lo*hi
            #pragma unroll
            for (int mt = 0; mt < 4; mt++) {
                uint32_t ad = st + TILE_B + (uint32_t)(warp_m * 64 + mt * 16 + group) * ROWB + kb + tig * 4;
                a[mt][0] = lds32(ad);
                a[mt][1] = lds32(ad + 8 * ROWB);
                a[mt][2] = lds32(ad + 16);
                a[mt][3] = lds32(ad + 8 * ROWB + 16);
            }
            #pragma unroll
            for (int mt = 0; mt < 4; mt++)
                #pragma unroll
                for (int nt = 0; nt < 4; nt++)
                    mma16816(acc[mt][nt], a[mt], bh[nt]);
        }

        if (++st_idx >= NSTAGE) st_idx = 0;
    }

    // Epilogue: s = cnorm[n] - 2*dot
    #pragma unroll
    for (int nt = 0; nt < 4; nt++) {
        const int n = n0 + warp_n * 32 + nt * 8 + tig * 2;
        const float2 cn = *(const float2*)(g_cnorm + n);
        #pragma unroll
        for (int mt = 0; mt < 4; mt++) {
            const int m = m0 + warp_m * 64 + mt * 16 + group;
            float2 o0, o1;
            o0.x = cn.x - 2.f * acc[mt][nt][0];
            o0.y = cn.y - 2.f * acc[mt][nt][1];
            o1.x = cn.x - 2.f * acc[mt][nt][2];
            o1.y = cn.y - 2.f * acc[mt][nt][3];
            *(float2*)(g_S + (size_t)m * CB + n) = o0;
            *(float2*)(g_S + (size_t)(m + 8) * CB + n) = o1;
        }
    }
}

// ---------------------------------------------------------------------------
// Kernel 2: per-row argmin(+double refinement), softmax -> probs,
//           gather -> quantized, loss accumulation, codes.
// ---------------------------------------------------------------------------
__global__ __launch_bounds__(256) void row_kernel(const float* __restrict__ slot,
                                                  const float* __restrict__ cb,
                                                  float* __restrict__ out) {
    const int row = blockIdx.x;
    const int tid = threadIdx.x;
    const float* srow = g_S + (size_t)row * CB;

    // --- load row, track local top-2 (first-occurrence tie-break) ---
    float v[16];
    float m1 = CUDART_INF_F, m2 = CUDART_INF_F;
    int   i1 = CB, i2 = CB;
    #pragma unroll
    for (int i = 0; i < 16; i++) {
        int idx = tid + i * 256;
        float x = srow[idx];
        v[i] = x;
        if (x < m1 || (x == m1 && idx < i1)) {
            m2 = m1; i2 = i1; m1 = x; i1 = idx;
        } else if (x < m2 || (x == m2 && idx < i2)) {
            m2 = x; i2 = idx;
        }
    }

    // --- block-wide top-2 reduction ---
    __shared__ float rm1[256], rm2[256];
    __shared__ int   ri1[256], ri2[256];
    rm1[tid] = m1; rm2[tid] = m2; ri1[tid] = i1; ri2[tid] = i2;
    __syncthreads();
    for (int s = 128; s > 0; s >>= 1) {
        if (tid < s) {
            float a1 = rm1[tid], b1 = rm1[tid + s];
            int   ai = ri1[tid], bi = ri1[tid + s];
            float a2 = rm2[tid], b2 = rm2[tid + s];
            int  a2i = ri2[tid], b2i = ri2[tid + s];
            bool af = (a1 < b1) || (a1 == b1 && ai < bi);
            if (af) {
                bool t = (a2 < b1) || (a2 == b1 && a2i < bi);
                rm2[tid] = t ? a2 : b1;  ri2[tid] = t ? a2i : bi;
            } else {
                rm1[tid] = b1; ri1[tid] = bi;
                bool t = (b2 < a1) || (b2 == a1 && b2i < ai);
                rm2[tid] = t ? b2 : a1;  ri2[tid] = t ? b2i : ai;
            }
        }
        __syncthreads();
    }
    const float gm1 = rm1[0]; const int gi1 = ri1[0];
    const float gm2 = rm2[0]; const int gi2 = ri2[0];
    __syncthreads();

    // --- rare-path double-precision refinement of argmin ---
    __shared__ int    s_code;
    __shared__ double sd[256];
    if (gm2 - gm1 < 1e-3f) {
        const float* x  = slot + (size_t)row * DIM;
        const float* c1 = cb + (size_t)gi1 * DIM;
        const float* c2 = cb + (size_t)gi2 * DIM;
        double d1 = 0.0, d2 = 0.0;
        for (int k = tid; k < DIM; k += 256) {
            double xv = (double)x[k];
            double a  = (double)c1[k];
            double b  = (double)c2[k];
            d1 += a * (a - 2.0 * xv);
            d2 += b * (b - 2.0 * xv);
        }
        sd[tid] = d1; __syncthreads();
        for (int s = 128; s > 0; s >>= 1) { if (tid < s) sd[tid] += sd[tid + s]; __syncthreads(); }
        double D1 = sd[0]; __syncthreads();
        sd[tid] = d2; __syncthreads();
        for (int s = 128; s > 0; s >>= 1) { if (tid < s) sd[tid] += sd[tid + s]; __syncthreads(); }
        double D2 = sd[0];
        if (tid == 0)
            s_code = (D2 < D1 || (D2 == D1 && gi2 < gi1)) ? gi2 : gi1;
    } else if (tid == 0) {
        s_code = gi1;
    }
    __syncthreads();
    const int code = s_code;

    // --- softmax over -s (row constant ||x||^2 cancels) ---
    float lsum = 0.f;
    #pragma unroll
    for (int i = 0; i < 16; i++) {
        float e = __expf(gm1 - v[i]);   // arg <= 0
        v[i] = e;
        lsum += e;
    }
    rm1[tid] = lsum; __syncthreads();
    for (int s = 128; s > 0; s >>= 1) { if (tid < s) rm1[tid] += rm1[tid + s]; __syncthreads(); }
    const float inv = 1.0f / rm1[0];
    float* probs = out + PROBS_OFF + (size_t)row * CB;
    #pragma unroll
    for (int i = 0; i < 16; i++)
        probs[tid + i * 256] = v[i] * inv;

    // --- quantized gather + loss contribution ---
    const float4* c4 = (const float4*)(cb + (size_t)code * DIM);
    const float4* x4 = (const float4*)(slot + (size_t)row * DIM);
    float4 q = c4[tid];
    float4 x = x4[tid];
    ((float4*)(out + QUANT_OFF + (size_t)row * DIM))[tid] = q;
    float dx = x.x - q.x, dy = x.y - q.y, dz = x.z - q.z, dw = x.w - q.w;
    float ls = dx * dx + dy * dy + dz * dz + dw * dw;

    __syncthreads();
    rm1[tid] = ls; __syncthreads();
    for (int s = 128; s > 0; s >>= 1) { if (tid < s) rm1[tid] += rm1[tid + s]; __syncthreads(); }
    if (tid == 0) {
        atomicAdd(&g_loss, (double)rm1[0]);
        out[CODES_OFF + row] = (float)code;
    }
}

// ---------------------------------------------------------------------------
// Kernel 3: finalize vq_loss = 1.25 * mean((x - q)^2)
// ---------------------------------------------------------------------------
__global__ void finish_kernel(float* __restrict__ out) {
    out[LOSS_OFF] = (float)(1.25 * g_loss / (double)((size_t)NROWS * DIM));
}

// ---------------------------------------------------------------------------
extern "C" void kernel_launch(void* const* d_in, const int* in_sizes, int n_in,
                              void* d_out, int out_size) {
    const float* slot = (const float*)d_in[0];   // [64,256,1024] f32
    const float* cb   = (const float*)d_in[1];   // [4096,1024]  f32
    float* out = (float*)d_out;

    // Dynamic smem opt-in (host-side attribute; idempotent; capture-safe)
    cudaFuncSetAttribute(gemm_kernel, cudaFuncAttributeMaxDynamicSharedMemorySize,
                         GEMM_SMEM_TOTAL);

    cnorm_kernel<<<CB, 256>>>(cb);
    split_kernel<<<(unsigned)((A_F4 + B_F4) / 256), 256>>>(slot, cb);
    dim3 grid(CB / GBN, NROWS / GBM);            // 32 x 128
    gemm_kernel<<<grid, 256, GEMM_SMEM_TOTAL>>>();
    row_kernel<<<NROWS, 256>>>(slot, cb, out);
    finish_kernel<<<1, 1>>>(out);
}